// round 11
// baseline (speedup 1.0000x reference)
#include <cuda_runtime.h>
#include <math.h>

#define C 64
#define MAX_N 65536
#define MAX_ETOT 2000000

// ---------------- device scratch (no allocation allowed) ----------------
__device__ int   g_deg[MAX_N];
__device__ int   g_hist[256];
__device__ int   g_hoff[256];
__device__ int   g_perm[MAX_N];
__device__ int   g_rowptr[MAX_N + 1];
__device__ int   g_fillptr[MAX_N];
__device__ int   g_col[MAX_ETOT];
__device__ __align__(256) float g_buf0[(size_t)MAX_N * C];
__device__ __align__(256) float g_buf1[(size_t)MAX_N * C];
__device__ __align__(256) float g_accum[(size_t)MAX_N * C];

// ---------------- CSR build ----------------

__global__ void k_init_deg(int n) {
    int i = blockIdx.x * blockDim.x + threadIdx.x;
    if (i < n) g_deg[i] = 1;                      // self loop
    if (i < 256) g_hist[i] = 0;
}

__global__ void k_count(const int* __restrict__ ei, int E) {
    int i = blockIdx.x * blockDim.x + threadIdx.x;
    if (i < E) atomicAdd(&g_deg[ei[E + i]], 1);   // dst row
}

// histogram of degrees, bin = 255 - min(deg,255)  (descending degree order)
__global__ void k_hist(int n) {
    int i = blockIdx.x * blockDim.x + threadIdx.x;
    if (i < n) {
        int d = min(g_deg[i], 255);
        atomicAdd(&g_hist[255 - d], 1);
    }
}

// single-block fused scan: rowptr/fillptr from deg, and exclusive scan of hist
__global__ void k_scan(int n, int etot) {
    __shared__ int sh[1024];
    int tid = threadIdx.x;
    int chunk = (n + 1023) >> 10;
    int s = tid * chunk, e = min(s + chunk, n);

    int sum = 0;
    for (int i = s; i < e; ++i) sum += g_deg[i];
    sh[tid] = sum;
    __syncthreads();
    #pragma unroll
    for (int off = 1; off < 1024; off <<= 1) {
        int t = (tid >= off) ? sh[tid - off] : 0;
        __syncthreads();
        sh[tid] += t;
        __syncthreads();
    }
    int run = sh[tid] - sum;                      // exclusive prefix
    for (int i = s; i < e; ++i) {
        g_rowptr[i] = run;
        g_fillptr[i] = run;
        run += g_deg[i];
    }
    if (tid == 0) g_rowptr[n] = etot;
    __syncthreads();

    // exclusive scan of 256-bin histogram
    int hv = (tid < 256) ? g_hist[tid] : 0;
    sh[tid] = hv;
    __syncthreads();
    #pragma unroll
    for (int off = 1; off < 256; off <<= 1) {
        int t = (tid >= off && tid < 256) ? sh[tid - off] : 0;
        __syncthreads();
        if (tid < 256) sh[tid] += t;
        __syncthreads();
    }
    if (tid < 256) g_hoff[tid] = sh[tid] - hv;
}

// scatter nodes into degree-sorted order (descending)
__global__ void k_perm(int n) {
    int i = blockIdx.x * blockDim.x + threadIdx.x;
    if (i < n) {
        int d = min(g_deg[i], 255);
        int pos = atomicAdd(&g_hoff[255 - d], 1);
        g_perm[pos] = i;
    }
}

__global__ void k_fill(const int* __restrict__ ei, int E, int n) {
    int i = blockIdx.x * blockDim.x + threadIdx.x;
    int tot = E + n;
    if (i >= tot) return;
    int src, dst;
    if (i < E) { src = ei[i]; dst = ei[E + i]; }
    else       { src = dst = i - E; }
    int pos = atomicAdd(&g_fillptr[dst], 1);
    g_col[pos] = src;
}

// ---------------- GAT layer: 4 nodes per warp, 8 lanes (8 ch each) per node --
// Nodes are taken through g_perm (degree-sorted) so the 4 nodes in a warp have
// near-equal degree -> md ~= deg, minimal padding iterations.
// xs features are double-buffered: iteration i computes on xs_cur while the
// LDGs for iteration i+1 are in flight (indices prefetched 2 ahead), removing
// the L2 gather latency from the serial chain.
// mode: 0 = first layer (accum = x + r), 1 = middle (accum += r),
//       2 = last (out = (accum + r) * 0.25)
__global__ __launch_bounds__(256)
void k_gat(const float* __restrict__ x,
           float* __restrict__ nxt,
           float* __restrict__ out,
           const float* __restrict__ att,    // [2,64] this layer
           const float* __restrict__ bias,   // [64]
           int n, int mode) {
    const unsigned FULL = 0xffffffffu;
    int lane = threadIdx.x & 31;
    int warp = (blockIdx.x * blockDim.x + threadIdx.x) >> 5;
    int grp  = lane >> 3;        // 0..3  : which node of this warp
    int li   = lane & 7;         // 0..7  : lane within group
    bool hi  = (lane & 4) != 0;  // upper quad of group -> owns head1 score

    int idx = warp * 4 + grp;
    bool nvalid = idx < n;
    int node = nvalid ? g_perm[idx] : 0;
    int safe_node = node;

    // per-lane channels: c = li*8 + k, k = 0..7
    int cbase = li * 8;
    float a0[8], a1[8], xd[8];
    {
        float4 t0 = *(const float4*)(att + cbase);
        float4 t1 = *(const float4*)(att + cbase + 4);
        a0[0]=t0.x; a0[1]=t0.y; a0[2]=t0.z; a0[3]=t0.w;
        a0[4]=t1.x; a0[5]=t1.y; a0[6]=t1.z; a0[7]=t1.w;
        float4 u0 = *(const float4*)(att + C + cbase);
        float4 u1 = *(const float4*)(att + C + cbase + 4);
        a1[0]=u0.x; a1[1]=u0.y; a1[2]=u0.z; a1[3]=u0.w;
        a1[4]=u1.x; a1[5]=u1.y; a1[6]=u1.z; a1[7]=u1.w;
    }
    {
        size_t ro = (size_t)safe_node * C + cbase;
        float4 d0 = *(const float4*)(x + ro);
        float4 d1 = *(const float4*)(x + ro + 4);
        xd[0]=d0.x; xd[1]=d0.y; xd[2]=d0.z; xd[3]=d0.w;
        xd[4]=d1.x; xd[5]=d1.y; xd[6]=d1.z; xd[7]=d1.w;
    }

    int beg = 0, end = 0;
    if (nvalid) { beg = g_rowptr[node]; end = g_rowptr[node + 1]; }
    int deg = end - beg;
    int md = deg;
    md = max(md, __shfl_xor_sync(FULL, md, 8));
    md = max(md, __shfl_xor_sync(FULL, md, 16));

    float acc0[8], acc1[8];
    #pragma unroll
    for (int k = 0; k < 8; ++k) { acc0[k] = 0.f; acc1[k] = 0.f; }
    float s_mine = 0.f;

    // pipeline prologue: xs for iter 0 in regs, index for iter 1 ready
    int src_cur = (0 < deg) ? g_col[beg] : safe_node;
    int src_nxt = (1 < deg) ? g_col[beg + 1] : safe_node;
    float xsc[8];
    {
        size_t ro = (size_t)src_cur * C + cbase;
        float4 s0 = *(const float4*)(x + ro);
        float4 s1 = *(const float4*)(x + ro + 4);
        xsc[0]=s0.x; xsc[1]=s0.y; xsc[2]=s0.z; xsc[3]=s0.w;
        xsc[4]=s1.x; xsc[5]=s1.y; xsc[6]=s1.z; xsc[7]=s1.w;
    }

    for (int i = 0; i < md; ++i) {
        // issue next iteration's feature loads immediately
        float xsn[8];
        {
            size_t ro = (size_t)src_nxt * C + cbase;
            float4 s0 = *(const float4*)(x + ro);
            float4 s1 = *(const float4*)(x + ro + 4);
            xsn[0]=s0.x; xsn[1]=s0.y; xsn[2]=s0.z; xsn[3]=s0.w;
            xsn[4]=s1.x; xsn[5]=s1.y; xsn[6]=s1.z; xsn[7]=s1.w;
        }
        int i2 = i + 2;
        int src_n2 = (i2 < deg) ? g_col[beg + i2] : safe_node;

        bool ev = (i < deg);

        float p0 = 0.f, p1 = 0.f;
        #pragma unroll
        for (int k = 0; k < 8; ++k) {
            float t = xd[k] + xsc[k];
            t = fmaxf(t, 0.2f * t);          // leaky_relu, slope 0.2
            p0 = fmaf(t, a0[k], p0);
            p1 = fmaf(t, a1[k], p1);
        }

        // group-of-8 reduce: fold heads across xor4, butterfly within quad
        float p0o = __shfl_xor_sync(FULL, p0, 4);
        float p1o = __shfl_xor_sync(FULL, p1, 4);
        float v = hi ? (p1 + p1o) : (p0 + p0o);
        v += __shfl_xor_sync(FULL, v, 2);
        v += __shfl_xor_sync(FULL, v, 1);

        float w_mine = ev ? __expf(v) : 0.f;
        float w_oth  = __shfl_xor_sync(FULL, w_mine, 4);
        float w0 = hi ? w_oth  : w_mine;
        float w1 = hi ? w_mine : w_oth;

        s_mine += w_mine;
        #pragma unroll
        for (int k = 0; k < 8; ++k) {
            acc0[k] = fmaf(w0, xsc[k], acc0[k]);
            acc1[k] = fmaf(w1, xsc[k], acc1[k]);
        }

        // rotate pipeline
        #pragma unroll
        for (int k = 0; k < 8; ++k) xsc[k] = xsn[k];
        src_nxt = src_n2;
    }

    if (!nvalid) return;

    float s_oth = __shfl_xor_sync(FULL, s_mine, 4);
    float s0 = hi ? s_oth : s_mine;
    float s1 = hi ? s_mine : s_oth;
    float inv0 = 1.f / (s0 + 1e-16f);
    float inv1 = 1.f / (s1 + 1e-16f);

    float r[8];
    {
        float4 b0 = *(const float4*)(bias + cbase);
        float4 b1 = *(const float4*)(bias + cbase + 4);
        float bb[8] = {b0.x,b0.y,b0.z,b0.w,b1.x,b1.y,b1.z,b1.w};
        #pragma unroll
        for (int k = 0; k < 8; ++k)
            r[k] = 0.5f * fmaf(acc0[k], inv0, acc1[k] * inv1) + bb[k];
    }

    size_t o = (size_t)node * C + cbase;
    if (mode == 2) {
        float4 ac0 = *(const float4*)(g_accum + o);
        float4 ac1 = *(const float4*)(g_accum + o + 4);
        float4 o0, o1;
        o0.x = (ac0.x + r[0]) * 0.25f; o0.y = (ac0.y + r[1]) * 0.25f;
        o0.z = (ac0.z + r[2]) * 0.25f; o0.w = (ac0.w + r[3]) * 0.25f;
        o1.x = (ac1.x + r[4]) * 0.25f; o1.y = (ac1.y + r[5]) * 0.25f;
        o1.z = (ac1.z + r[6]) * 0.25f; o1.w = (ac1.w + r[7]) * 0.25f;
        *(float4*)(out + o)     = o0;
        *(float4*)(out + o + 4) = o1;
    } else {
        *(float4*)(nxt + o)     = make_float4(r[0], r[1], r[2], r[3]);
        *(float4*)(nxt + o + 4) = make_float4(r[4], r[5], r[6], r[7]);
        float4 ac0, ac1;
        if (mode == 0) {
            ac0 = make_float4(xd[0]+r[0], xd[1]+r[1], xd[2]+r[2], xd[3]+r[3]);
            ac1 = make_float4(xd[4]+r[4], xd[5]+r[5], xd[6]+r[6], xd[7]+r[7]);
        } else {
            ac0 = *(const float4*)(g_accum + o);
            ac1 = *(const float4*)(g_accum + o + 4);
            ac0.x += r[0]; ac0.y += r[1]; ac0.z += r[2]; ac0.w += r[3];
            ac1.x += r[4]; ac1.y += r[5]; ac1.z += r[6]; ac1.w += r[7];
        }
        *(float4*)(g_accum + o)     = ac0;
        *(float4*)(g_accum + o + 4) = ac1;
    }
}

// ---------------- host launcher ----------------
extern "C" void kernel_launch(void* const* d_in, const int* in_sizes, int n_in,
                              void* d_out, int out_size) {
    const float* x    = (const float*)d_in[0];   // [N, 64]
    const int*   ei   = (const int*)d_in[1];     // [2, E]
    const float* att  = (const float*)d_in[2];   // [L, 2, 64]
    const float* bias = (const float*)d_in[3];   // [L, 64]
    float* out = (float*)d_out;

    int n    = in_sizes[0] / C;
    int E    = in_sizes[1] / 2;
    int etot = E + n;

    float *buf0, *buf1;
    cudaGetSymbolAddress((void**)&buf0, g_buf0);
    cudaGetSymbolAddress((void**)&buf1, g_buf1);

    const int T = 256;
    // ---- CSR build + degree-sorted node permutation ----
    k_init_deg<<<(n + T - 1) / T, T>>>(n);
    k_count<<<(E + T - 1) / T, T>>>(ei, E);
    k_hist<<<(n + T - 1) / T, T>>>(n);
    k_scan<<<1, 1024>>>(n, etot);
    k_perm<<<(n + T - 1) / T, T>>>(n);
    k_fill<<<(etot + T - 1) / T, T>>>(ei, E, n);

    // ---- 3 GAT layers: 256 thr = 8 warps = 32 nodes per block ----
    int gb = (n + 31) / 32;
    k_gat<<<gb, 256>>>(x,    buf0, out, att,         bias,         n, 0);
    k_gat<<<gb, 256>>>(buf0, buf1, out, att + 2 * C, bias + C,     n, 1);
    k_gat<<<gb, 256>>>(buf1, buf0, out, att + 4 * C, bias + 2 * C, n, 2);
}

// round 13
// speedup vs baseline: 1.5536x; 1.5536x over previous
#include <cuda_runtime.h>
#include <math.h>

#define C 64
#define MAX_N 65536
#define MAX_ETOT 2000000

// ---------------- device scratch (no allocation allowed) ----------------
__device__ int   g_deg[MAX_N];        // counts REAL edges only (self loop implicit)
__device__ int   g_incl[MAX_N];
__device__ int   g_bsum[256];
__device__ int   g_hist[256];
__device__ int   g_hoff[256];
__device__ int   g_perm[MAX_N];
__device__ int   g_rowptr[MAX_N + 1];
__device__ int   g_fillptr[MAX_N];
__device__ int   g_col[MAX_ETOT];
__device__ __align__(256) float g_buf0[(size_t)MAX_N * C];
__device__ __align__(256) float g_buf1[(size_t)MAX_N * C];
__device__ __align__(256) float g_accum[(size_t)MAX_N * C];

// ---------------- CSR build ----------------

__global__ void k_count(const int* __restrict__ ei, int E) {
    int i = blockIdx.x * blockDim.x + threadIdx.x;
    if (i < E) atomicAdd(&g_deg[ei[E + i]], 1);   // dst row
}

// per-block inclusive scan of g_deg (1024/block) + smem-aggregated degree
// histogram (bin = 255 - min(deg+1,255), descending total degree)
__global__ void k_scan_block(int n) {
    __shared__ int sh[1024];
    __shared__ int lh[256];
    int tid = threadIdx.x;
    if (tid < 256) lh[tid] = 0;
    int i = blockIdx.x * 1024 + tid;
    int v = (i < n) ? g_deg[i] : 0;
    sh[tid] = v;
    __syncthreads();
    #pragma unroll
    for (int off = 1; off < 1024; off <<= 1) {
        int t = (tid >= off) ? sh[tid - off] : 0;
        __syncthreads();
        sh[tid] += t;
        __syncthreads();
    }
    if (i < n) {
        g_incl[i] = sh[tid];
        int d = min(v + 1, 255);                  // +1 = self loop
        atomicAdd(&lh[255 - d], 1);
    }
    if (tid == 1023) g_bsum[blockIdx.x] = sh[1023];
    __syncthreads();
    if (tid < 256 && lh[tid]) atomicAdd(&g_hist[tid], lh[tid]);
}

// one block, 256 threads: exclusive scan of block sums (nb<=64) AND of the
// 256-bin histogram
__global__ void k_scan_small(int nb) {
    __shared__ int sh[256];
    int t = threadIdx.x;
    int v = (t < nb) ? g_bsum[t] : 0;
    sh[t] = v;
    __syncthreads();
    #pragma unroll
    for (int off = 1; off < 64; off <<= 1) {
        int u = (t >= off) ? sh[t - off] : 0;
        __syncthreads();
        sh[t] += u;
        __syncthreads();
    }
    if (t < nb) g_bsum[t] = sh[t] - v;
    __syncthreads();
    int hv = g_hist[t];
    sh[t] = hv;
    __syncthreads();
    #pragma unroll
    for (int off = 1; off < 256; off <<= 1) {
        int u = (t >= off) ? sh[t - off] : 0;
        __syncthreads();
        sh[t] += u;
        __syncthreads();
    }
    g_hoff[t] = sh[t] - hv;
}

// rowptr/fillptr (+i makes the self loop implicit) + degree-sorted scatter
__global__ void k_rowptr_perm(int n, int etot) {
    int i = blockIdx.x * blockDim.x + threadIdx.x;
    if (i < n) {
        int deg = g_deg[i];
        int ex = g_incl[i] - deg + g_bsum[i >> 10] + i;
        g_rowptr[i] = ex;
        g_fillptr[i] = ex;
        int d = min(deg + 1, 255);
        int pos = atomicAdd(&g_hoff[255 - d], 1);
        g_perm[pos] = i;
    }
    if (i == 0) g_rowptr[n] = etot;
}

__global__ void k_fill(const int* __restrict__ ei, int E, int n) {
    int i = blockIdx.x * blockDim.x + threadIdx.x;
    int tot = E + n;
    if (i >= tot) return;
    int src, dst;
    if (i < E) { src = ei[i]; dst = ei[E + i]; }
    else       { src = dst = i - E; }
    int pos = atomicAdd(&g_fillptr[dst], 1);
    g_col[pos] = src;
}

// ---------------- GAT layer: 4 nodes per warp, 8 lanes (8 ch each) per node --
// Nodes taken through g_perm (degree-sorted) -> md ~= deg within each warp.
// xs features double-buffered: compute on xs_cur while iteration i+1's LDGs
// are in flight (indices prefetched 2 ahead).
// mode: 0 = first layer (accum = x + r), 1 = middle (accum += r),
//       2 = last (out = (accum + r) * 0.25)
__global__ __launch_bounds__(256)
void k_gat(const float* __restrict__ x,
           float* __restrict__ nxt,
           float* __restrict__ out,
           const float* __restrict__ att,    // [2,64] this layer
           const float* __restrict__ bias,   // [64]
           int n, int mode) {
    const unsigned FULL = 0xffffffffu;
    int lane = threadIdx.x & 31;
    int warp = (blockIdx.x * blockDim.x + threadIdx.x) >> 5;
    int grp  = lane >> 3;
    int li   = lane & 7;
    bool hi  = (lane & 4) != 0;

    int idx = warp * 4 + grp;
    bool nvalid = idx < n;
    int node = nvalid ? g_perm[idx] : 0;
    int safe_node = node;

    int cbase = li * 8;
    float a0[8], a1[8], xd[8];
    {
        float4 t0 = *(const float4*)(att + cbase);
        float4 t1 = *(const float4*)(att + cbase + 4);
        a0[0]=t0.x; a0[1]=t0.y; a0[2]=t0.z; a0[3]=t0.w;
        a0[4]=t1.x; a0[5]=t1.y; a0[6]=t1.z; a0[7]=t1.w;
        float4 u0 = *(const float4*)(att + C + cbase);
        float4 u1 = *(const float4*)(att + C + cbase + 4);
        a1[0]=u0.x; a1[1]=u0.y; a1[2]=u0.z; a1[3]=u0.w;
        a1[4]=u1.x; a1[5]=u1.y; a1[6]=u1.z; a1[7]=u1.w;
    }
    {
        size_t ro = (size_t)safe_node * C + cbase;
        float4 d0 = *(const float4*)(x + ro);
        float4 d1 = *(const float4*)(x + ro + 4);
        xd[0]=d0.x; xd[1]=d0.y; xd[2]=d0.z; xd[3]=d0.w;
        xd[4]=d1.x; xd[5]=d1.y; xd[6]=d1.z; xd[7]=d1.w;
    }

    int beg = 0, end = 0;
    if (nvalid) { beg = g_rowptr[node]; end = g_rowptr[node + 1]; }
    int deg = end - beg;
    int md = deg;
    md = max(md, __shfl_xor_sync(FULL, md, 8));
    md = max(md, __shfl_xor_sync(FULL, md, 16));

    float acc0[8], acc1[8];
    #pragma unroll
    for (int k = 0; k < 8; ++k) { acc0[k] = 0.f; acc1[k] = 0.f; }
    float s_mine = 0.f;

    int src_cur = (0 < deg) ? g_col[beg] : safe_node;
    int src_nxt = (1 < deg) ? g_col[beg + 1] : safe_node;
    float xsc[8];
    {
        size_t ro = (size_t)src_cur * C + cbase;
        float4 s0 = *(const float4*)(x + ro);
        float4 s1 = *(const float4*)(x + ro + 4);
        xsc[0]=s0.x; xsc[1]=s0.y; xsc[2]=s0.z; xsc[3]=s0.w;
        xsc[4]=s1.x; xsc[5]=s1.y; xsc[6]=s1.z; xsc[7]=s1.w;
    }

    for (int i = 0; i < md; ++i) {
        float xsn[8];
        {
            size_t ro = (size_t)src_nxt * C + cbase;
            float4 s0 = *(const float4*)(x + ro);
            float4 s1 = *(const float4*)(x + ro + 4);
            xsn[0]=s0.x; xsn[1]=s0.y; xsn[2]=s0.z; xsn[3]=s0.w;
            xsn[4]=s1.x; xsn[5]=s1.y; xsn[6]=s1.z; xsn[7]=s1.w;
        }
        int i2 = i + 2;
        int src_n2 = (i2 < deg) ? g_col[beg + i2] : safe_node;

        bool ev = (i < deg);

        float p0 = 0.f, p1 = 0.f;
        #pragma unroll
        for (int k = 0; k < 8; ++k) {
            float t = xd[k] + xsc[k];
            t = fmaxf(t, 0.2f * t);          // leaky_relu, slope 0.2
            p0 = fmaf(t, a0[k], p0);
            p1 = fmaf(t, a1[k], p1);
        }

        float p0o = __shfl_xor_sync(FULL, p0, 4);
        float p1o = __shfl_xor_sync(FULL, p1, 4);
        float v = hi ? (p1 + p1o) : (p0 + p0o);
        v += __shfl_xor_sync(FULL, v, 2);
        v += __shfl_xor_sync(FULL, v, 1);

        float w_mine = ev ? __expf(v) : 0.f;
        float w_oth  = __shfl_xor_sync(FULL, w_mine, 4);
        float w0 = hi ? w_oth  : w_mine;
        float w1 = hi ? w_mine : w_oth;

        s_mine += w_mine;
        #pragma unroll
        for (int k = 0; k < 8; ++k) {
            acc0[k] = fmaf(w0, xsc[k], acc0[k]);
            acc1[k] = fmaf(w1, xsc[k], acc1[k]);
        }

        #pragma unroll
        for (int k = 0; k < 8; ++k) xsc[k] = xsn[k];
        src_nxt = src_n2;
    }

    if (!nvalid) return;

    float s_oth = __shfl_xor_sync(FULL, s_mine, 4);
    float s0 = hi ? s_oth : s_mine;
    float s1 = hi ? s_mine : s_oth;
    float inv0 = 1.f / (s0 + 1e-16f);
    float inv1 = 1.f / (s1 + 1e-16f);

    float r[8];
    {
        float4 b0 = *(const float4*)(bias + cbase);
        float4 b1 = *(const float4*)(bias + cbase + 4);
        float bb[8] = {b0.x,b0.y,b0.z,b0.w,b1.x,b1.y,b1.z,b1.w};
        #pragma unroll
        for (int k = 0; k < 8; ++k)
            r[k] = 0.5f * fmaf(acc0[k], inv0, acc1[k] * inv1) + bb[k];
    }

    size_t o = (size_t)node * C + cbase;
    if (mode == 2) {
        float4 ac0 = *(const float4*)(g_accum + o);
        float4 ac1 = *(const float4*)(g_accum + o + 4);
        float4 o0, o1;
        o0.x = (ac0.x + r[0]) * 0.25f; o0.y = (ac0.y + r[1]) * 0.25f;
        o0.z = (ac0.z + r[2]) * 0.25f; o0.w = (ac0.w + r[3]) * 0.25f;
        o1.x = (ac1.x + r[4]) * 0.25f; o1.y = (ac1.y + r[5]) * 0.25f;
        o1.z = (ac1.z + r[6]) * 0.25f; o1.w = (ac1.w + r[7]) * 0.25f;
        *(float4*)(out + o)     = o0;
        *(float4*)(out + o + 4) = o1;
    } else {
        *(float4*)(nxt + o)     = make_float4(r[0], r[1], r[2], r[3]);
        *(float4*)(nxt + o + 4) = make_float4(r[4], r[5], r[6], r[7]);
        float4 ac0, ac1;
        if (mode == 0) {
            ac0 = make_float4(xd[0]+r[0], xd[1]+r[1], xd[2]+r[2], xd[3]+r[3]);
            ac1 = make_float4(xd[4]+r[4], xd[5]+r[5], xd[6]+r[6], xd[7]+r[7]);
        } else {
            ac0 = *(const float4*)(g_accum + o);
            ac1 = *(const float4*)(g_accum + o + 4);
            ac0.x += r[0]; ac0.y += r[1]; ac0.z += r[2]; ac0.w += r[3];
            ac1.x += r[4]; ac1.y += r[5]; ac1.z += r[6]; ac1.w += r[7];
        }
        *(float4*)(g_accum + o)     = ac0;
        *(float4*)(g_accum + o + 4) = ac1;
    }
}

// ---------------- host launcher ----------------
extern "C" void kernel_launch(void* const* d_in, const int* in_sizes, int n_in,
                              void* d_out, int out_size) {
    const float* x    = (const float*)d_in[0];   // [N, 64]
    const int*   ei   = (const int*)d_in[1];     // [2, E]
    const float* att  = (const float*)d_in[2];   // [L, 2, 64]
    const float* bias = (const float*)d_in[3];   // [L, 64]
    float* out = (float*)d_out;

    int n    = in_sizes[0] / C;
    int E    = in_sizes[1] / 2;
    int etot = E + n;

    float *buf0, *buf1;
    cudaGetSymbolAddress((void**)&buf0, g_buf0);
    cudaGetSymbolAddress((void**)&buf1, g_buf1);
    int *degp, *histp;
    cudaGetSymbolAddress((void**)&degp, g_deg);
    cudaGetSymbolAddress((void**)&histp, g_hist);

    const int T = 256;
    // ---- CSR build + degree-sorted permutation (5 kernels + 2 memsets) ----
    cudaMemsetAsync(degp, 0, n * sizeof(int));
    cudaMemsetAsync(histp, 0, 256 * sizeof(int));
    k_count<<<(E + T - 1) / T, T>>>(ei, E);
    int nb = (n + 1023) / 1024;
    k_scan_block<<<nb, 1024>>>(n);
    k_scan_small<<<1, 256>>>(nb);
    k_rowptr_perm<<<(n + T - 1) / T, T>>>(n, etot);
    k_fill<<<(etot + T - 1) / T, T>>>(ei, E, n);

    // ---- 3 GAT layers: 256 thr = 8 warps = 32 nodes per block ----
    int gb = (n + 31) / 32;
    k_gat<<<gb, 256>>>(x,    buf0, out, att,         bias,         n, 0);
    k_gat<<<gb, 256>>>(buf0, buf1, out, att + 2 * C, bias + C,     n, 1);
    k_gat<<<gb, 256>>>(buf1, buf0, out, att + 4 * C, bias + 2 * C, n, 2);
}

// round 14
// speedup vs baseline: 1.5740x; 1.0131x over previous
#include <cuda_runtime.h>
#include <math.h>

#define C 64
#define MAX_N 65536
#define MAX_ETOT 2000000

// ---------------- device scratch (no allocation allowed) ----------------
__device__ int   g_deg[MAX_N];        // counts REAL edges only (self loop implicit)
__device__ int   g_incl[MAX_N];
__device__ int   g_bsum[256];
__device__ int   g_hist[256];
__device__ int   g_hoff[256];
__device__ int   g_perm[MAX_N];
__device__ int   g_rowptr[MAX_N + 1];
__device__ int   g_fillptr[MAX_N];
__device__ int   g_col[MAX_ETOT];
__device__ __align__(256) float g_buf0[(size_t)MAX_N * C];
__device__ __align__(256) float g_buf1[(size_t)MAX_N * C];
__device__ __align__(256) float g_accum[(size_t)MAX_N * C];

// ---------------- CSR build ----------------

__global__ void k_count(const int* __restrict__ ei, int E) {
    int i = blockIdx.x * blockDim.x + threadIdx.x;
    if (i < E) atomicAdd(&g_deg[ei[E + i]], 1);   // dst row
}

// per-block inclusive scan of g_deg (1024/block) + smem-aggregated degree
// histogram (bin = 255 - min(deg+1,255), descending total degree)
__global__ void k_scan_block(int n) {
    __shared__ int sh[1024];
    __shared__ int lh[256];
    int tid = threadIdx.x;
    if (tid < 256) lh[tid] = 0;
    int i = blockIdx.x * 1024 + tid;
    int v = (i < n) ? g_deg[i] : 0;
    sh[tid] = v;
    __syncthreads();
    #pragma unroll
    for (int off = 1; off < 1024; off <<= 1) {
        int t = (tid >= off) ? sh[tid - off] : 0;
        __syncthreads();
        sh[tid] += t;
        __syncthreads();
    }
    if (i < n) {
        g_incl[i] = sh[tid];
        int d = min(v + 1, 255);                  // +1 = self loop
        atomicAdd(&lh[255 - d], 1);
    }
    if (tid == 1023) g_bsum[blockIdx.x] = sh[1023];
    __syncthreads();
    if (tid < 256 && lh[tid]) atomicAdd(&g_hist[tid], lh[tid]);
}

// one block, 256 threads: exclusive scan of block sums (nb<=64) AND of the
// 256-bin histogram
__global__ void k_scan_small(int nb) {
    __shared__ int sh[256];
    int t = threadIdx.x;
    int v = (t < nb) ? g_bsum[t] : 0;
    sh[t] = v;
    __syncthreads();
    #pragma unroll
    for (int off = 1; off < 64; off <<= 1) {
        int u = (t >= off) ? sh[t - off] : 0;
        __syncthreads();
        sh[t] += u;
        __syncthreads();
    }
    if (t < nb) g_bsum[t] = sh[t] - v;
    __syncthreads();
    int hv = g_hist[t];
    sh[t] = hv;
    __syncthreads();
    #pragma unroll
    for (int off = 1; off < 256; off <<= 1) {
        int u = (t >= off) ? sh[t - off] : 0;
        __syncthreads();
        sh[t] += u;
        __syncthreads();
    }
    g_hoff[t] = sh[t] - hv;
}

// rowptr/fillptr (+i makes self loop implicit) + degree-sorted scatter.
// Two-level scatter: smem per-block bin counts, ONE global atomic per
// (block,bin) to reserve a range, then conflict-free writes.
__global__ void k_rowptr_perm(int n, int etot) {
    __shared__ int lcnt[256];
    __shared__ int lbase[256];
    int tid = threadIdx.x;
    lcnt[tid] = 0;
    __syncthreads();
    int i = blockIdx.x * blockDim.x + tid;
    bool valid = i < n;
    int bin = 0, myoff = 0;
    if (valid) {
        int deg = g_deg[i];
        int ex = g_incl[i] - deg + g_bsum[i >> 10] + i;
        g_rowptr[i] = ex;
        g_fillptr[i] = ex;
        int d = min(deg + 1, 255);
        bin = 255 - d;
        myoff = atomicAdd(&lcnt[bin], 1);
    }
    __syncthreads();
    if (lcnt[tid]) lbase[tid] = atomicAdd(&g_hoff[tid], lcnt[tid]);
    __syncthreads();
    if (valid) g_perm[lbase[bin] + myoff] = i;
    if (i == 0) g_rowptr[n] = etot;
}

__global__ void k_fill(const int* __restrict__ ei, int E, int n) {
    int i = blockIdx.x * blockDim.x + threadIdx.x;
    int tot = E + n;
    if (i >= tot) return;
    int src, dst;
    if (i < E) { src = ei[i]; dst = ei[E + i]; }
    else       { src = dst = i - E; }
    int pos = atomicAdd(&g_fillptr[dst], 1);
    g_col[pos] = src;
}

// ---------------- GAT layer: 4 nodes per warp, 8 lanes (8 ch each) per node --
// Degree-sorted nodes (g_perm) -> md ~= deg within each warp.
// Mainloop unrolled x2 with dual feature buffers X/Y and dual prefetched
// indices sA/sB: no register rotate, full-iteration index->feature distance.
// mode: 0 = first layer (accum = x + r), 1 = middle (accum += r),
//       2 = last (out = (accum + r) * 0.25)
__global__ __launch_bounds__(256)
void k_gat(const float* __restrict__ x,
           float* __restrict__ nxt,
           float* __restrict__ out,
           const float* __restrict__ att,    // [2,64] this layer
           const float* __restrict__ bias,   // [64]
           int n, int mode) {
    const unsigned FULL = 0xffffffffu;
    int lane = threadIdx.x & 31;
    int warp = (blockIdx.x * blockDim.x + threadIdx.x) >> 5;
    int grp  = lane >> 3;
    int li   = lane & 7;
    bool hi  = (lane & 4) != 0;

    int idx = warp * 4 + grp;
    bool nvalid = idx < n;
    int node = nvalid ? g_perm[idx] : 0;
    int safe_node = node;

    int cbase = li * 8;
    float a0[8], a1[8], xd[8];
    {
        float4 t0 = *(const float4*)(att + cbase);
        float4 t1 = *(const float4*)(att + cbase + 4);
        a0[0]=t0.x; a0[1]=t0.y; a0[2]=t0.z; a0[3]=t0.w;
        a0[4]=t1.x; a0[5]=t1.y; a0[6]=t1.z; a0[7]=t1.w;
        float4 u0 = *(const float4*)(att + C + cbase);
        float4 u1 = *(const float4*)(att + C + cbase + 4);
        a1[0]=u0.x; a1[1]=u0.y; a1[2]=u0.z; a1[3]=u0.w;
        a1[4]=u1.x; a1[5]=u1.y; a1[6]=u1.z; a1[7]=u1.w;
    }
    {
        size_t ro = (size_t)safe_node * C + cbase;
        float4 d0 = *(const float4*)(x + ro);
        float4 d1 = *(const float4*)(x + ro + 4);
        xd[0]=d0.x; xd[1]=d0.y; xd[2]=d0.z; xd[3]=d0.w;
        xd[4]=d1.x; xd[5]=d1.y; xd[6]=d1.z; xd[7]=d1.w;
    }

    int beg = 0, end = 0;
    if (nvalid) { beg = g_rowptr[node]; end = g_rowptr[node + 1]; }
    int deg = end - beg;
    int md = deg;
    md = max(md, __shfl_xor_sync(FULL, md, 8));
    md = max(md, __shfl_xor_sync(FULL, md, 16));
    int md2 = (md + 1) & ~1;

    float acc0[8], acc1[8];
    #pragma unroll
    for (int k = 0; k < 8; ++k) { acc0[k] = 0.f; acc1[k] = 0.f; }
    float s_mine = 0.f;

    auto loadf = [&](int src, float* dst8) {
        size_t ro = (size_t)src * C + cbase;
        float4 s0 = *(const float4*)(x + ro);
        float4 s1 = *(const float4*)(x + ro + 4);
        dst8[0]=s0.x; dst8[1]=s0.y; dst8[2]=s0.z; dst8[3]=s0.w;
        dst8[4]=s1.x; dst8[5]=s1.y; dst8[6]=s1.z; dst8[7]=s1.w;
    };

    auto edge_update = [&](const float* xs, bool ev) {
        float p0 = 0.f, p1 = 0.f;
        #pragma unroll
        for (int k = 0; k < 8; ++k) {
            float t = xd[k] + xs[k];
            t = fmaxf(t, 0.2f * t);          // leaky_relu, slope 0.2
            p0 = fmaf(t, a0[k], p0);
            p1 = fmaf(t, a1[k], p1);
        }
        float p0o = __shfl_xor_sync(FULL, p0, 4);
        float p1o = __shfl_xor_sync(FULL, p1, 4);
        float v = hi ? (p1 + p1o) : (p0 + p0o);
        v += __shfl_xor_sync(FULL, v, 2);
        v += __shfl_xor_sync(FULL, v, 1);

        float w_mine = ev ? __expf(v) : 0.f;
        float w_oth  = __shfl_xor_sync(FULL, w_mine, 4);
        float w0 = hi ? w_oth  : w_mine;
        float w1 = hi ? w_mine : w_oth;

        s_mine += w_mine;
        #pragma unroll
        for (int k = 0; k < 8; ++k) {
            acc0[k] = fmaf(w0, xs[k], acc0[k]);
            acc1[k] = fmaf(w1, xs[k], acc1[k]);
        }
    };

    // prologue: X=edge0, Y=edge1, indices for edges 2 and 3
    float X[8], Y[8];
    loadf((0 < deg) ? g_col[beg]     : safe_node, X);
    loadf((1 < deg) ? g_col[beg + 1] : safe_node, Y);
    int sA = (2 < deg) ? g_col[beg + 2] : safe_node;
    int sB = (3 < deg) ? g_col[beg + 3] : safe_node;

    for (int i = 0; i < md2; i += 2) {
        // sub A: edge i from X; reload X <- edge i+2; prefetch idx i+4
        edge_update(X, i < deg);
        loadf(sA, X);
        sA = (i + 4 < deg) ? g_col[beg + i + 4] : safe_node;
        // sub B: edge i+1 from Y; reload Y <- edge i+3; prefetch idx i+5
        edge_update(Y, i + 1 < deg);
        loadf(sB, Y);
        sB = (i + 5 < deg) ? g_col[beg + i + 5] : safe_node;
    }

    if (!nvalid) return;

    float s_oth = __shfl_xor_sync(FULL, s_mine, 4);
    float s0 = hi ? s_oth : s_mine;
    float s1 = hi ? s_mine : s_oth;
    float inv0 = 1.f / (s0 + 1e-16f);
    float inv1 = 1.f / (s1 + 1e-16f);

    float r[8];
    {
        float4 b0 = *(const float4*)(bias + cbase);
        float4 b1 = *(const float4*)(bias + cbase + 4);
        float bb[8] = {b0.x,b0.y,b0.z,b0.w,b1.x,b1.y,b1.z,b1.w};
        #pragma unroll
        for (int k = 0; k < 8; ++k)
            r[k] = 0.5f * fmaf(acc0[k], inv0, acc1[k] * inv1) + bb[k];
    }

    size_t o = (size_t)node * C + cbase;
    if (mode == 2) {
        float4 ac0 = *(const float4*)(g_accum + o);
        float4 ac1 = *(const float4*)(g_accum + o + 4);
        float4 o0, o1;
        o0.x = (ac0.x + r[0]) * 0.25f; o0.y = (ac0.y + r[1]) * 0.25f;
        o0.z = (ac0.z + r[2]) * 0.25f; o0.w = (ac0.w + r[3]) * 0.25f;
        o1.x = (ac1.x + r[4]) * 0.25f; o1.y = (ac1.y + r[5]) * 0.25f;
        o1.z = (ac1.z + r[6]) * 0.25f; o1.w = (ac1.w + r[7]) * 0.25f;
        *(float4*)(out + o)     = o0;
        *(float4*)(out + o + 4) = o1;
    } else {
        *(float4*)(nxt + o)     = make_float4(r[0], r[1], r[2], r[3]);
        *(float4*)(nxt + o + 4) = make_float4(r[4], r[5], r[6], r[7]);
        float4 ac0, ac1;
        if (mode == 0) {
            ac0 = make_float4(xd[0]+r[0], xd[1]+r[1], xd[2]+r[2], xd[3]+r[3]);
            ac1 = make_float4(xd[4]+r[4], xd[5]+r[5], xd[6]+r[6], xd[7]+r[7]);
        } else {
            ac0 = *(const float4*)(g_accum + o);
            ac1 = *(const float4*)(g_accum + o + 4);
            ac0.x += r[0]; ac0.y += r[1]; ac0.z += r[2]; ac0.w += r[3];
            ac1.x += r[4]; ac1.y += r[5]; ac1.z += r[6]; ac1.w += r[7];
        }
        *(float4*)(g_accum + o)     = ac0;
        *(float4*)(g_accum + o + 4) = ac1;
    }
}

// ---------------- host launcher ----------------
extern "C" void kernel_launch(void* const* d_in, const int* in_sizes, int n_in,
                              void* d_out, int out_size) {
    const float* x    = (const float*)d_in[0];   // [N, 64]
    const int*   ei   = (const int*)d_in[1];     // [2, E]
    const float* att  = (const float*)d_in[2];   // [L, 2, 64]
    const float* bias = (const float*)d_in[3];   // [L, 64]
    float* out = (float*)d_out;

    int n    = in_sizes[0] / C;
    int E    = in_sizes[1] / 2;
    int etot = E + n;

    float *buf0, *buf1;
    cudaGetSymbolAddress((void**)&buf0, g_buf0);
    cudaGetSymbolAddress((void**)&buf1, g_buf1);
    int *degp, *histp;
    cudaGetSymbolAddress((void**)&degp, g_deg);
    cudaGetSymbolAddress((void**)&histp, g_hist);

    const int T = 256;
    // ---- CSR build + degree-sorted permutation ----
    cudaMemsetAsync(degp, 0, n * sizeof(int));
    cudaMemsetAsync(histp, 0, 256 * sizeof(int));
    k_count<<<(E + T - 1) / T, T>>>(ei, E);
    int nb = (n + 1023) / 1024;
    k_scan_block<<<nb, 1024>>>(n);
    k_scan_small<<<1, 256>>>(nb);
    k_rowptr_perm<<<(n + T - 1) / T, T>>>(n, etot);
    k_fill<<<(etot + T - 1) / T, T>>>(ei, E, n);

    // ---- 3 GAT layers: 256 thr = 8 warps = 32 nodes per block ----
    int gb = (n + 31) / 32;
    k_gat<<<gb, 256>>>(x,    buf0, out, att,         bias,         n, 0);
    k_gat<<<gb, 256>>>(buf0, buf1, out, att + 2 * C, bias + C,     n, 1);
    k_gat<<<gb, 256>>>(buf1, buf0, out, att + 4 * C, bias + 2 * C, n, 2);
}